// round 4
// baseline (speedup 1.0000x reference)
#include <cuda_runtime.h>
#include <cstdint>
#include <cstddef>

#define E_EXP 16
#define T_TOK 512
#define H_DIM 1024
#define I_DIM 4096

// Does this device-compilation pass support tcgen05 (arch-specific sm_10xa)?
#if defined(__CUDA_ARCH__) && (defined(__CUDA_ARCH_FEAT_SM103_ALL) || defined(__CUDA_ARCH_FEAT_SM100_ALL) || defined(__CUDA_ARCH_FEAT_SM101_ALL) || defined(__CUDA_ARCH_SPECIFIC__))
#define TCGEN_OK 1
#else
#define TCGEN_OK 0
#endif

// Scratch (__device__ globals: allocation-free rule)
__device__ float g_Xr [(size_t)E_EXP * T_TOK * H_DIM];   // rounded X        [e][t][h]
__device__ float g_W1t[(size_t)E_EXP * I_DIM * H_DIM];   // rounded W1^T     [e][i][h]  (n-major, k contig)
__device__ float g_W2t[(size_t)E_EXP * H_DIM * I_DIM];   // rounded W2^T     [e][h][i]
__device__ float g_h  [(size_t)E_EXP * T_TOK * I_DIM];   // intermediate (tf32-rounded)

// ---------------- common helpers ----------------
__device__ __forceinline__ uint32_t smem_to_u32(const void* p) {
    uint32_t a;
    asm("{ .reg .u64 t; cvta.to.shared.u64 t, %1; cvt.u32.u64 %0, t; }" : "=r"(a) : "l"(p));
    return a;
}
__device__ __forceinline__ uint32_t swz128(uint32_t o) { return o ^ ((o >> 3) & 0x70); }
__device__ __forceinline__ void cp_async16(uint32_t s, const void* g) {
    asm volatile("cp.async.cg.shared.global [%0], [%1], 16;" :: "r"(s), "l"(g));
}
// RN-round fp32 -> tf32 bit pattern (low 13 bits zero); exact no-op for HW cvt
__device__ __forceinline__ float rn_tf32(float x) {
    uint32_t b = __float_as_uint(x);
    b = (b + 0xFFFu + ((b >> 13) & 1u)) & 0xFFFFE000u;
    return __uint_as_float(b);
}

#if TCGEN_OK
// ---------------- tcgen05-only helpers ----------------
__device__ __forceinline__ uint32_t elect_one_pred() {
    uint32_t pred;
    asm volatile("{\n\t.reg .pred p;\n\telect.sync _|p, 0xFFFFFFFF;\n\tselp.b32 %0, 1, 0, p;\n\t}" : "=r"(pred));
    return pred;
}
#define MBARRIER_INIT(addr, count) \
    asm volatile("mbarrier.init.shared.b64 [%0], %1;" :: "r"((uint32_t)(addr)), "r"((uint32_t)(count)) : "memory")
#define MBARRIER_WAIT_PARITY(a, pp) do { \
    uint32_t _m = (uint32_t)(a); uint32_t _p = (uint32_t)(pp); uint32_t _d; \
    asm volatile("{\n\t.reg .pred p;\n\tmbarrier.try_wait.parity.acquire.cta.shared::cta.b64 p, [%1], %2;\n\tselp.b32 %0, 1, 0, p;\n\t}" \
        : "=r"(_d) : "r"(_m), "r"(_p) : "memory"); \
    if (!_d) { \
        asm volatile("{\n\t.reg .pred P1;\n\tWL_%=:\n\tmbarrier.try_wait.parity.acquire.cta.shared::cta.b64 P1, [%0], %1, 0x989680;\n\t@P1 bra.uni WD_%=;\n\tbra.uni WL_%=;\n\tWD_%=:\n\t}" \
            :: "r"(_m), "r"(_p) : "memory"); \
    } \
} while (0)
#define TCGEN05_ALLOC(sa, n) \
    asm volatile("tcgen05.alloc.cta_group::1.sync.aligned.shared::cta.b32 [%0], %1;" :: "r"((uint32_t)(sa)), "r"((uint32_t)(n)) : "memory")
#define TCGEN05_DEALLOC(t, n) \
    asm volatile("tcgen05.dealloc.cta_group::1.sync.aligned.b32 %0, %1;" :: "r"(t), "r"((uint32_t)(n)))
#define TCGEN05_RELINQ() asm volatile("tcgen05.relinquish_alloc_permit.cta_group::1.sync.aligned;")
#define TCGEN05_COMMIT(m) \
    asm volatile("tcgen05.commit.cta_group::1.mbarrier::arrive::one.shared::cluster.b64 [%0];" :: "r"((uint32_t)(m)) : "memory")
#define TCGEN05_WAIT_LD()  asm volatile("tcgen05.wait::ld.sync.aligned;" ::: "memory")
#define TCGEN05_FENCE_BEFORE() asm volatile("tcgen05.fence::before_thread_sync;" ::: "memory")
#define TCGEN05_FENCE_AFTER()  asm volatile("tcgen05.fence::after_thread_sync;" ::: "memory")
#define FENCE_ASYNC() asm volatile("fence.proxy.async.shared::cta;" ::: "memory")

#define TCGEN05_LD_32X32B_X32(r, ta) \
    asm volatile("tcgen05.ld.sync.aligned.32x32b.x32.b32 " \
        "{%0, %1, %2, %3, %4, %5, %6, %7, %8, %9, %10, %11, %12, %13, %14, %15, " \
        " %16, %17, %18, %19, %20, %21, %22, %23, %24, %25, %26, %27, %28, %29, %30, %31}, [%32];" \
        : "=r"((r)[0]),  "=r"((r)[1]),  "=r"((r)[2]),  "=r"((r)[3]), \
          "=r"((r)[4]),  "=r"((r)[5]),  "=r"((r)[6]),  "=r"((r)[7]), \
          "=r"((r)[8]),  "=r"((r)[9]),  "=r"((r)[10]), "=r"((r)[11]), \
          "=r"((r)[12]), "=r"((r)[13]), "=r"((r)[14]), "=r"((r)[15]), \
          "=r"((r)[16]), "=r"((r)[17]), "=r"((r)[18]), "=r"((r)[19]), \
          "=r"((r)[20]), "=r"((r)[21]), "=r"((r)[22]), "=r"((r)[23]), \
          "=r"((r)[24]), "=r"((r)[25]), "=r"((r)[26]), "=r"((r)[27]), \
          "=r"((r)[28]), "=r"((r)[29]), "=r"((r)[30]), "=r"((r)[31]) \
        : "r"(ta))

static constexpr uint64_t DESC_SW128 =
    (uint64_t(2) << 61) | (uint64_t(1) << 46) | (uint64_t(64) << 32) | (uint64_t(1) << 16);
#define MAKE_DESC(a) (DESC_SW128 | ((uint64_t)((a) >> 4) & 0x3FFF))

__device__ __forceinline__ void cp_async_arrive(uint32_t bar) {
    asm volatile("cp.async.mbarrier.arrive.noinc.shared.b64 [%0];" :: "r"(bar));
}
__device__ __forceinline__ void mma_tf32_ss(uint32_t d, uint64_t ad, uint64_t bd,
                                            uint32_t idesc, uint32_t en) {
    asm volatile("{\n\t.reg .pred p;\n\tsetp.ne.u32 p, %4, 0;\n\t"
        "tcgen05.mma.cta_group::1.kind::tf32 [%0], %1, %2, %3, {%5, %5, %5, %5}, p;\n\t}"
        :: "r"(d), "l"(ad), "l"(bd), "r"(idesc), "r"(en), "r"(0u) : "memory");
}
#endif // TCGEN_OK

// ---------------- Prep: round X ----------------
__global__ void round_x_kernel(const float4* __restrict__ in) {
    size_t i = (size_t)blockIdx.x * blockDim.x + threadIdx.x;
    float4 v = in[i];
    v.x = rn_tf32(v.x); v.y = rn_tf32(v.y); v.z = rn_tf32(v.z); v.w = rn_tf32(v.w);
    reinterpret_cast<float4*>(g_Xr)[i] = v;
}

// ---------------- Prep: round + transpose weights to [n][k] ----------------
template <int WHICH>
__global__ void transpose_round_kernel(const float* __restrict__ in) {
    constexpr int R = (WHICH == 0) ? H_DIM : I_DIM;  // input rows (k)
    constexpr int C = (WHICH == 0) ? I_DIM : H_DIM;  // input cols (n)
    float* out = (WHICH == 0) ? g_W1t : g_W2t;
    __shared__ float tile[32][33];
    int e = blockIdx.z;
    const float* pin = in + (size_t)e * R * C;
    float* pout = out + (size_t)e * R * C;
    int tx = threadIdx.x, ty = threadIdx.y;
    int c0 = blockIdx.x * 32, r0 = blockIdx.y * 32;
#pragma unroll
    for (int j = 0; j < 4; j++)
        tile[ty + j * 8][tx] = rn_tf32(pin[(size_t)(r0 + ty + j * 8) * C + c0 + tx]);
    __syncthreads();
#pragma unroll
    for (int j = 0; j < 4; j++)
        pout[(size_t)(c0 + ty + j * 8) * R + r0 + tx] = tile[tx][ty + j * 8];
}

// ============================================================================
// Grouped GEMM: C[e,m,n] = sum_k A[e,m,k]*B[e,n,k] + bias[e,n]
// CTA tile 128x128, KC=32, 4 stages. Two bodies:
//   TCGEN_OK: tcgen05 kind::tf32 SS, TMEM accumulator
//   else    : mma.sync m16n8k8 tf32, ldmatrix fragments
// WHICH=0: A=g_Xr (K=H), B=g_W1t, N=I, C=g_h (rounded)
// WHICH=1: A=g_h  (K=I), B=g_W2t, N=H, C=out
// ============================================================================
template <int KT, int NTOT, int WHICH>
__global__ __launch_bounds__(256, 1)
void gemm_tf32_kernel(const float* __restrict__ bias, float* __restrict__ outC) {
    constexpr int TM = 128, TN = 128, KC = 32, STAGES = 4;
    constexpr int ABYTES = TM * KC * 4;   // 16 KB
    constexpr int BBYTES = TN * KC * 4;   // 16 KB
    constexpr int KITERS = KT / KC;

    const float* A = (WHICH == 0) ? g_Xr : g_h;
    const float* B = (WHICH == 0) ? g_W1t : g_W2t;
    float* Cb = (WHICH == 0) ? g_h : outC;

    extern __shared__ char smem[];
    uint32_t sbase = smem_to_u32(smem);
    float* bias_s = (float*)(smem + 2048);
    uint32_t tiles = (sbase + 3072 + 1023) & ~1023u;

    int tid = threadIdx.x, wid = tid >> 5, lane = tid & 31;
    int mt = blockIdx.x, nt = blockIdx.y, e = blockIdx.z;

    const float* Ab = A + ((size_t)e * T_TOK + (size_t)mt * TM) * KT;
    const float* Bb = B + ((size_t)e * NTOT + (size_t)nt * TN) * KT;

    if (tid < TN) bias_s[tid] = bias[(size_t)e * NTOT + (size_t)nt * TN + tid];

#if TCGEN_OK
    // ------------------------------------------------------------------
    // tcgen05 path: warps 0-6 produce (224 thr), warp 7 MMA, warps 0-3 epi
    // ------------------------------------------------------------------
    constexpr uint32_t IDESC =
        (1u << 4) | (2u << 7) | (2u << 10) | ((TN / 8) << 17) | ((TM / 16) << 24);
    uint32_t full0  = sbase;          // 4 x 8B
    uint32_t empty0 = sbase + 64;     // 4 x 8B
    uint32_t doneb  = sbase + 128;
    uint32_t tslot  = sbase + 136;

    if (tid == 0) {
#pragma unroll
        for (int s = 0; s < STAGES; s++) {
            MBARRIER_INIT(full0 + 8 * s, 224);
            MBARRIER_INIT(empty0 + 8 * s, 1);
        }
        MBARRIER_INIT(doneb, 1);
    }
    if (wid == 7) TCGEN05_ALLOC(tslot, 128);
    __syncthreads();

    uint32_t tmem;
    asm volatile("ld.shared.b32 %0, [%1];" : "=r"(tmem) : "r"(tslot));

    if (wid < 7) {
        for (int it = 0; it < KITERS; ++it) {
            int s = it & 3;
            MBARRIER_WAIT_PARITY(empty0 + 8 * s, 1 ^ ((it >> 2) & 1));
            const float* aB = Ab + it * KC;
            const float* bB = Bb + it * KC;
            uint32_t aS = tiles + s * ABYTES;
            uint32_t bS = tiles + STAGES * ABYTES + s * BBYTES;
#pragma unroll
            for (int c0 = 0; c0 < 10; c0++) {
                int c = tid + c0 * 224;
                if (c < 2048) {
                    if (c < 1024) {
                        int r = c >> 3, k = c & 7;
                        cp_async16(aS + swz128((uint32_t)(r * 128 + k * 16)),
                                   aB + (size_t)r * KT + k * 4);
                    } else {
                        int cc = c - 1024;
                        int r = cc >> 3, k = cc & 7;
                        cp_async16(bS + swz128((uint32_t)(r * 128 + k * 16)),
                                   bB + (size_t)r * KT + k * 4);
                    }
                }
            }
            cp_async_arrive(full0 + 8 * s);
        }
    } else {
        for (int it = 0; it < KITERS; ++it) {
            int s = it & 3;
            MBARRIER_WAIT_PARITY(full0 + 8 * s, (it >> 2) & 1);
            FENCE_ASYNC();
            uint64_t ad = MAKE_DESC(tiles + s * ABYTES);
            uint64_t bd = MAKE_DESC(tiles + STAGES * ABYTES + s * BBYTES);
            if (elect_one_pred()) {
#pragma unroll
                for (int k = 0; k < 4; k++)   // 4 x K=8 tf32 dispatches, +32B each
                    mma_tf32_ss(tmem, ad + 2 * k, bd + 2 * k, IDESC,
                                (it > 0 || k > 0) ? 1u : 0u);
                TCGEN05_COMMIT(empty0 + 8 * s);
            }
        }
        if (elect_one_pred()) TCGEN05_COMMIT(doneb);
    }

    if (wid < 4) {
        MBARRIER_WAIT_PARITY(doneb, 0);
        TCGEN05_FENCE_AFTER();
        float* Crow = Cb + ((size_t)(e * T_TOK + mt * TM + wid * 32 + lane)) * NTOT
                         + (size_t)nt * TN;
#pragma unroll 1
        for (int c0 = 0; c0 < 4; c0++) {
            uint32_t regs[32];
            TCGEN05_LD_32X32B_X32(regs, tmem + c0 * 32);
            TCGEN05_WAIT_LD();
            float4 v[8];
#pragma unroll
            for (int j = 0; j < 32; j++) {
                float x = __uint_as_float(regs[j]) + bias_s[c0 * 32 + j];
                if (WHICH == 0) x = rn_tf32(x);
                ((float*)v)[j] = x;
            }
#pragma unroll
            for (int q = 0; q < 8; q++)
                reinterpret_cast<float4*>(Crow + c0 * 32)[q] = v[q];
        }
        TCGEN05_FENCE_BEFORE();
    }
    __syncthreads();
    if (wid == 7) {
        TCGEN05_RELINQ();
        TCGEN05_DEALLOC(tmem, 128);
    }
#else
    // ------------------------------------------------------------------
    // Fallback: mma.sync m16n8k8 tf32. 8 warps (2m x 4n), warp tile 64x32.
    // ------------------------------------------------------------------
    const int m0w = (wid & 1) * 64;
    const int n0w = (wid >> 1) * 32;
    const int q = lane >> 3, rr = lane & 7;

    float acc[4][4][4];
#pragma unroll
    for (int mi = 0; mi < 4; mi++)
#pragma unroll
        for (int ni = 0; ni < 4; ni++)
#pragma unroll
            for (int j = 0; j < 4; j++) acc[mi][ni][j] = 0.f;

    auto issue_stage = [&](int it) {
        int s = it & 3;
        const float* aB = Ab + it * KC;
        const float* bB = Bb + it * KC;
        uint32_t aS = tiles + s * ABYTES;
        uint32_t bS = tiles + STAGES * ABYTES + s * BBYTES;
#pragma unroll
        for (int c0 = 0; c0 < 8; c0++) {
            int c = tid + c0 * 256;
            if (c < 1024) {
                int r = c >> 3, k = c & 7;
                cp_async16(aS + swz128((uint32_t)(r * 128 + k * 16)),
                           aB + (size_t)r * KT + k * 4);
            } else {
                int cc = c - 1024;
                int r = cc >> 3, k = cc & 7;
                cp_async16(bS + swz128((uint32_t)(r * 128 + k * 16)),
                           bB + (size_t)r * KT + k * 4);
            }
        }
        asm volatile("cp.async.commit_group;" ::: "memory");
    };

#pragma unroll 1
    for (int it = 0; it < STAGES - 1; ++it) issue_stage(it);

#pragma unroll 1
    for (int it = 0; it < KITERS; ++it) {
        if (it + STAGES - 1 < KITERS) issue_stage(it + STAGES - 1);
        else asm volatile("cp.async.commit_group;" ::: "memory");
        asm volatile("cp.async.wait_group 2;" ::: "memory");
        __syncthreads();

        int s = it & 3;
        uint32_t aS = tiles + s * ABYTES;
        uint32_t bS = tiles + STAGES * ABYTES + s * BBYTES;
#pragma unroll
        for (int ks = 0; ks < 4; ks++) {
            uint32_t af[4][4];
#pragma unroll
            for (int mi = 0; mi < 4; mi++) {
                int row = m0w + mi * 16 + (q & 1) * 8 + rr;
                int col4 = (ks * 8 + (q >> 1) * 4) * 4;
                uint32_t ad = aS + swz128((uint32_t)(row * 128 + col4));
                asm volatile("ldmatrix.sync.aligned.m8n8.x4.shared.b16 {%0,%1,%2,%3}, [%4];"
                    : "=r"(af[mi][0]), "=r"(af[mi][1]), "=r"(af[mi][2]), "=r"(af[mi][3])
                    : "r"(ad));
            }
            uint32_t bf[4][2];
#pragma unroll
            for (int j = 0; j < 2; j++) {
                int row = n0w + j * 16 + (q >> 1) * 8 + rr;
                int col4 = (ks * 8 + (q & 1) * 4) * 4;
                uint32_t bd = bS + swz128((uint32_t)(row * 128 + col4));
                asm volatile("ldmatrix.sync.aligned.m8n8.x4.shared.b16 {%0,%1,%2,%3}, [%4];"
                    : "=r"(bf[2 * j][0]), "=r"(bf[2 * j][1]),
                      "=r"(bf[2 * j + 1][0]), "=r"(bf[2 * j + 1][1])
                    : "r"(bd));
            }
#pragma unroll
            for (int mi = 0; mi < 4; mi++)
#pragma unroll
                for (int ni = 0; ni < 4; ni++) {
                    asm volatile(
                        "mma.sync.aligned.m16n8k8.row.col.f32.tf32.tf32.f32 "
                        "{%0,%1,%2,%3}, {%4,%5,%6,%7}, {%8,%9}, {%0,%1,%2,%3};"
                        : "+f"(acc[mi][ni][0]), "+f"(acc[mi][ni][1]),
                          "+f"(acc[mi][ni][2]), "+f"(acc[mi][ni][3])
                        : "r"(af[mi][0]), "r"(af[mi][1]), "r"(af[mi][2]), "r"(af[mi][3]),
                          "r"(bf[ni][0]), "r"(bf[ni][1]));
                }
        }
        __syncthreads();
    }

    // epilogue
    {
        int gr = lane >> 2, gc = (lane & 3) * 2;
        size_t rowbase = (size_t)(e * T_TOK + mt * TM + m0w + gr);
#pragma unroll
        for (int mi = 0; mi < 4; mi++) {
#pragma unroll
            for (int ni = 0; ni < 4; ni++) {
                int col = n0w + ni * 8 + gc;
                float b0 = bias_s[col], b1 = bias_s[col + 1];
                float2 v0, v1;
                v0.x = acc[mi][ni][0] + b0; v0.y = acc[mi][ni][1] + b1;
                v1.x = acc[mi][ni][2] + b0; v1.y = acc[mi][ni][3] + b1;
                if (WHICH == 0) {
                    v0.x = rn_tf32(v0.x); v0.y = rn_tf32(v0.y);
                    v1.x = rn_tf32(v1.x); v1.y = rn_tf32(v1.y);
                }
                size_t r0 = (rowbase + mi * 16) * NTOT + (size_t)nt * TN + col;
                *reinterpret_cast<float2*>(Cb + r0) = v0;
                *reinterpret_cast<float2*>(Cb + r0 + 8 * NTOT) = v1;
            }
        }
    }
#endif
}

// ---------------- launch ----------------
extern "C" void kernel_launch(void* const* d_in, const int* in_sizes, int n_in,
                              void* d_out, int out_size) {
    const float* X  = (const float*)d_in[0];
    const float* W1 = (const float*)d_in[1];
    const float* b1 = (const float*)d_in[2];
    const float* W2 = (const float*)d_in[3];
    const float* b2 = (const float*)d_in[4];
    float* out = (float*)d_out;

    constexpr int SMEM = 3072 + 1024 + 8 * 128 * 32 * 4;  // hdr+bias+align, 128KB tiles
    cudaFuncSetAttribute(gemm_tf32_kernel<H_DIM, I_DIM, 0>,
                         cudaFuncAttributeMaxDynamicSharedMemorySize, SMEM);
    cudaFuncSetAttribute(gemm_tf32_kernel<I_DIM, H_DIM, 1>,
                         cudaFuncAttributeMaxDynamicSharedMemorySize, SMEM);

    // prep: RN-round to tf32 bit patterns (+ transpose weights to [n][k])
    round_x_kernel<<<(E_EXP * T_TOK * H_DIM) / (4 * 256), 256>>>((const float4*)X);
    transpose_round_kernel<0><<<dim3(I_DIM / 32, H_DIM / 32, E_EXP), dim3(32, 8)>>>(W1);
    transpose_round_kernel<1><<<dim3(H_DIM / 32, I_DIM / 32, E_EXP), dim3(32, 8)>>>(W2);

    // GEMM1: h = X @ W1 + b1
    gemm_tf32_kernel<H_DIM, I_DIM, 0>
        <<<dim3(T_TOK / 128, I_DIM / 128, E_EXP), 256, SMEM>>>(b1, nullptr);
    // GEMM2: y = h @ W2 + b2
    gemm_tf32_kernel<I_DIM, H_DIM, 1>
        <<<dim3(T_TOK / 128, H_DIM / 128, E_EXP), 256, SMEM>>>(b2, out);
}

// round 5
// speedup vs baseline: 1.1129x; 1.1129x over previous
#include <cuda_runtime.h>
#include <cuda.h>
#include <cstdint>
#include <cstddef>

#define E_EXP 16
#define T_TOK 512
#define H_DIM 1024
#define I_DIM 4096

// Does this device-compilation pass support tcgen05 (arch-specific sm_10xa)?
#if defined(__CUDA_ARCH__) && (defined(__CUDA_ARCH_FEAT_SM103_ALL) || defined(__CUDA_ARCH_FEAT_SM100_ALL) || defined(__CUDA_ARCH_FEAT_SM101_ALL) || defined(__CUDA_ARCH_SPECIFIC__))
#define TCGEN_OK 1
#else
#define TCGEN_OK 0
#endif

// Scratch (__device__ globals: allocation-free rule)
__device__ float g_Xr [(size_t)E_EXP * T_TOK * H_DIM];   // rounded X        [e][t][h]
__device__ float g_W1t[(size_t)E_EXP * I_DIM * H_DIM];   // rounded W1^T     [e][i][h]
__device__ float g_W2t[(size_t)E_EXP * H_DIM * I_DIM];   // rounded W2^T     [e][h][i]
__device__ float g_h  [(size_t)E_EXP * T_TOK * I_DIM];   // intermediate (tf32-rounded)

// ---------------- common helpers ----------------
__device__ __forceinline__ uint32_t smem_to_u32(const void* p) {
    uint32_t a;
    asm("{ .reg .u64 t; cvta.to.shared.u64 t, %1; cvt.u32.u64 %0, t; }" : "=r"(a) : "l"(p));
    return a;
}
// RN-round fp32 -> tf32 bit pattern (low 13 bits zero); exact no-op for HW cvt
__device__ __forceinline__ float rn_tf32(float x) {
    uint32_t b = __float_as_uint(x);
    b = (b + 0xFFFu + ((b >> 13) & 1u)) & 0xFFFFE000u;
    return __uint_as_float(b);
}

#if TCGEN_OK
// ---------------- tcgen05/TMA helpers (sm_103a pass only) ----------------
__device__ __forceinline__ uint32_t elect_one_pred() {
    uint32_t pred;
    asm volatile("{\n\t.reg .pred p;\n\telect.sync _|p, 0xFFFFFFFF;\n\tselp.b32 %0, 1, 0, p;\n\t}" : "=r"(pred));
    return pred;
}
#define MBARRIER_INIT(addr, count) \
    asm volatile("mbarrier.init.shared.b64 [%0], %1;" :: "r"((uint32_t)(addr)), "r"((uint32_t)(count)) : "memory")
#define MBARRIER_EXPECT_TX(addr, bytes) \
    asm volatile("mbarrier.arrive.expect_tx.shared.b64 _, [%0], %1;" :: "r"((uint32_t)(addr)), "r"((uint32_t)(bytes)) : "memory")
#define MBARRIER_WAIT_PARITY(a, pp) do { \
    uint32_t _m = (uint32_t)(a); uint32_t _p = (uint32_t)(pp); uint32_t _d; \
    asm volatile("{\n\t.reg .pred p;\n\tmbarrier.try_wait.parity.acquire.cta.shared::cta.b64 p, [%1], %2;\n\tselp.b32 %0, 1, 0, p;\n\t}" \
        : "=r"(_d) : "r"(_m), "r"(_p) : "memory"); \
    if (!_d) { \
        asm volatile("{\n\t.reg .pred P1;\n\tWL_%=:\n\tmbarrier.try_wait.parity.acquire.cta.shared::cta.b64 P1, [%0], %1, 0x989680;\n\t@P1 bra.uni WD_%=;\n\tbra.uni WL_%=;\n\tWD_%=:\n\t}" \
            :: "r"(_m), "r"(_p) : "memory"); \
    } \
} while (0)
#define TCGEN05_ALLOC(sa, n) \
    asm volatile("tcgen05.alloc.cta_group::1.sync.aligned.shared::cta.b32 [%0], %1;" :: "r"((uint32_t)(sa)), "r"((uint32_t)(n)) : "memory")
#define TCGEN05_DEALLOC(t, n) \
    asm volatile("tcgen05.dealloc.cta_group::1.sync.aligned.b32 %0, %1;" :: "r"(t), "r"((uint32_t)(n)))
#define TCGEN05_RELINQ() asm volatile("tcgen05.relinquish_alloc_permit.cta_group::1.sync.aligned;")
#define TCGEN05_COMMIT(m) \
    asm volatile("tcgen05.commit.cta_group::1.mbarrier::arrive::one.shared::cluster.b64 [%0];" :: "r"((uint32_t)(m)) : "memory")
#define TCGEN05_WAIT_LD()  asm volatile("tcgen05.wait::ld.sync.aligned;" ::: "memory")
#define TCGEN05_FENCE_BEFORE() asm volatile("tcgen05.fence::before_thread_sync;" ::: "memory")
#define TCGEN05_FENCE_AFTER()  asm volatile("tcgen05.fence::after_thread_sync;" ::: "memory")
#define FENCE_ASYNC() asm volatile("fence.proxy.async.shared::cta;" ::: "memory")

#define TMA_LOAD_3D(smem_addr, tensor_map, cx, cy, cz, mbar) \
    asm volatile("cp.async.bulk.tensor.3d.shared::cta.global.tile.mbarrier::complete_tx::bytes " \
                 "[%0], [%1, {%2, %3, %4}], [%5];" \
                 :: "r"((uint32_t)(smem_addr)), "l"(tensor_map), \
                    "r"((int32_t)(cx)), "r"((int32_t)(cy)), "r"((int32_t)(cz)), \
                    "r"((uint32_t)(mbar)) : "memory")

#define TCGEN05_LD_32X32B_X32(r, ta) \
    asm volatile("tcgen05.ld.sync.aligned.32x32b.x32.b32 " \
        "{%0, %1, %2, %3, %4, %5, %6, %7, %8, %9, %10, %11, %12, %13, %14, %15, " \
        " %16, %17, %18, %19, %20, %21, %22, %23, %24, %25, %26, %27, %28, %29, %30, %31}, [%32];" \
        : "=r"((r)[0]),  "=r"((r)[1]),  "=r"((r)[2]),  "=r"((r)[3]), \
          "=r"((r)[4]),  "=r"((r)[5]),  "=r"((r)[6]),  "=r"((r)[7]), \
          "=r"((r)[8]),  "=r"((r)[9]),  "=r"((r)[10]), "=r"((r)[11]), \
          "=r"((r)[12]), "=r"((r)[13]), "=r"((r)[14]), "=r"((r)[15]), \
          "=r"((r)[16]), "=r"((r)[17]), "=r"((r)[18]), "=r"((r)[19]), \
          "=r"((r)[20]), "=r"((r)[21]), "=r"((r)[22]), "=r"((r)[23]), \
          "=r"((r)[24]), "=r"((r)[25]), "=r"((r)[26]), "=r"((r)[27]), \
          "=r"((r)[28]), "=r"((r)[29]), "=r"((r)[30]), "=r"((r)[31]) \
        : "r"(ta))

static constexpr uint64_t DESC_SW128 =
    (uint64_t(2) << 61) | (uint64_t(1) << 46) | (uint64_t(64) << 32) | (uint64_t(1) << 16);
#define MAKE_DESC(a) (DESC_SW128 | ((uint64_t)((a) >> 4) & 0x3FFF))

__device__ __forceinline__ void mma_tf32_ss(uint32_t d, uint64_t ad, uint64_t bd,
                                            uint32_t idesc, uint32_t en) {
    asm volatile("{\n\t.reg .pred p;\n\tsetp.ne.u32 p, %4, 0;\n\t"
        "tcgen05.mma.cta_group::1.kind::tf32 [%0], %1, %2, %3, {%5, %5, %5, %5}, p;\n\t}"
        :: "r"(d), "l"(ad), "l"(bd), "r"(idesc), "r"(en), "r"(0u) : "memory");
}
#endif // TCGEN_OK

// ---------------- Prep: round X ----------------
__global__ void round_x_kernel(const float4* __restrict__ in) {
    size_t i = (size_t)blockIdx.x * blockDim.x + threadIdx.x;
    float4 v = in[i];
    v.x = rn_tf32(v.x); v.y = rn_tf32(v.y); v.z = rn_tf32(v.z); v.w = rn_tf32(v.w);
    reinterpret_cast<float4*>(g_Xr)[i] = v;
}

// ---------------- Prep: round + transpose weights to [n][k] ----------------
template <int WHICH>
__global__ void transpose_round_kernel(const float* __restrict__ in) {
    constexpr int R = (WHICH == 0) ? H_DIM : I_DIM;  // input rows (k)
    constexpr int C = (WHICH == 0) ? I_DIM : H_DIM;  // input cols (n)
    float* out = (WHICH == 0) ? g_W1t : g_W2t;
    __shared__ float tile[32][33];
    int e = blockIdx.z;
    const float* pin = in + (size_t)e * R * C;
    float* pout = out + (size_t)e * R * C;
    int tx = threadIdx.x, ty = threadIdx.y;
    int c0 = blockIdx.x * 32, r0 = blockIdx.y * 32;
#pragma unroll
    for (int j = 0; j < 4; j++)
        tile[ty + j * 8][tx] = rn_tf32(pin[(size_t)(r0 + ty + j * 8) * C + c0 + tx]);
    __syncthreads();
#pragma unroll
    for (int j = 0; j < 4; j++)
        pout[(size_t)(c0 + ty + j * 8) * R + r0 + tx] = tile[tx][ty + j * 8];
}

// ============================================================================
// Grouped GEMM: C[e,m,n] = sum_k A[e,m,k]*B[e,n,k] + bias[e,n]
// CTA tile 128x256, KC=32, 4 stages, TMA producers, tcgen05 tf32 SS MMA.
// WHICH=0: A=g_Xr (K=H), B=g_W1t, N=I, C=g_h (rounded)
// WHICH=1: A=g_h  (K=I), B=g_W2t, N=H, C=out
// ============================================================================
template <int KT, int NTOT, int WHICH>
__global__ __launch_bounds__(256, 1)
void gemm_tf32_kernel(const __grid_constant__ CUtensorMap tmA,
                      const __grid_constant__ CUtensorMap tmB,
                      const float* __restrict__ bias, float* __restrict__ outC) {
    constexpr int TM = 128, TN = 256, KC = 32, STAGES = 4;
    constexpr int ABYTES = TM * KC * 4;   // 16 KB
    constexpr int BBYTES = TN * KC * 4;   // 32 KB
    constexpr int KITERS = KT / KC;

    float* Cb = (WHICH == 0) ? g_h : outC;

    extern __shared__ char smem[];
    uint32_t sbase = smem_to_u32(smem);
    float* bias_s = (float*)(smem + 2048);              // 256 floats
    uint32_t tiles = (sbase + 3072 + 1023) & ~1023u;    // 1024-aligned

    int tid = threadIdx.x, wid = tid >> 5, lane = tid & 31;
    int mt = blockIdx.x, nt = blockIdx.y, e = blockIdx.z;

    if (tid < TN) bias_s[tid] = bias[(size_t)e * NTOT + (size_t)nt * TN + tid];

#if TCGEN_OK
    constexpr uint32_t IDESC =
        (1u << 4) | (2u << 7) | (2u << 10) | ((TN / 8) << 17) | ((TM / 16) << 24);
    uint32_t full0  = sbase;          // 4 x 8B
    uint32_t empty0 = sbase + 64;     // 4 x 8B
    uint32_t doneb  = sbase + 128;
    uint32_t tslot  = sbase + 136;

    if (tid == 0) {
#pragma unroll
        for (int s = 0; s < STAGES; s++) {
            MBARRIER_INIT(full0 + 8 * s, 1);    // flips via expect_tx + TMA complete
            MBARRIER_INIT(empty0 + 8 * s, 1);   // flips via tcgen05.commit
        }
        MBARRIER_INIT(doneb, 1);
        FENCE_ASYNC();
    }
    if (wid == 7) TCGEN05_ALLOC(tslot, 256);
    __syncthreads();

    uint32_t tmem;
    asm volatile("ld.shared.b32 %0, [%1];" : "=r"(tmem) : "r"(tslot));

    if (wid == 7 && elect_one_pred()) {
        // prologue: fill all stages
#pragma unroll
        for (int p = 0; p < STAGES; ++p) {
            uint32_t fb = full0 + 8 * p;
            MBARRIER_EXPECT_TX(fb, ABYTES + BBYTES);
            TMA_LOAD_3D(tiles + p * ABYTES, &tmA, p * KC, mt * TM, e, fb);
            TMA_LOAD_3D(tiles + STAGES * ABYTES + p * BBYTES, &tmB, p * KC, nt * TN, e, fb);
        }
        // mainloop
#pragma unroll 1
        for (int it = 0; it < KITERS; ++it) {
            int s = it & 3;
            int ph = (it >> 2) & 1;
            MBARRIER_WAIT_PARITY(full0 + 8 * s, ph);
            uint64_t ad = MAKE_DESC(tiles + s * ABYTES);
            uint64_t bd = MAKE_DESC(tiles + STAGES * ABYTES + s * BBYTES);
#pragma unroll
            for (int k = 0; k < 4; k++)   // 4 x K=8 tf32 dispatches, +32B each
                mma_tf32_ss(tmem, ad + 2 * k, bd + 2 * k, IDESC,
                            (it > 0 || k > 0) ? 1u : 0u);
            TCGEN05_COMMIT(empty0 + 8 * s);
            if (it + STAGES < KITERS) {
                // wait until the MMAs reading stage s have completed, then refill
                MBARRIER_WAIT_PARITY(empty0 + 8 * s, ph);
                uint32_t fb = full0 + 8 * s;
                MBARRIER_EXPECT_TX(fb, ABYTES + BBYTES);
                TMA_LOAD_3D(tiles + s * ABYTES, &tmA, (it + STAGES) * KC, mt * TM, e, fb);
                TMA_LOAD_3D(tiles + STAGES * ABYTES + s * BBYTES, &tmB,
                            (it + STAGES) * KC, nt * TN, e, fb);
            }
        }
        TCGEN05_COMMIT(doneb);
    }

    // epilogue: warps 0-3 read TMEM rows, add bias, store
    if (wid < 4) {
        MBARRIER_WAIT_PARITY(doneb, 0);
        TCGEN05_FENCE_AFTER();
        float* Crow = Cb + ((size_t)(e * T_TOK + mt * TM + wid * 32 + lane)) * NTOT
                         + (size_t)nt * TN;
#pragma unroll 1
        for (int c0 = 0; c0 < TN / 32; c0++) {
            uint32_t regs[32];
            TCGEN05_LD_32X32B_X32(regs, tmem + c0 * 32);
            TCGEN05_WAIT_LD();
            float4 v[8];
#pragma unroll
            for (int j = 0; j < 32; j++) {
                float x = __uint_as_float(regs[j]) + bias_s[c0 * 32 + j];
                if (WHICH == 0) x = rn_tf32(x);
                ((float*)v)[j] = x;
            }
#pragma unroll
            for (int q = 0; q < 8; q++)
                reinterpret_cast<float4*>(Crow + c0 * 32)[q] = v[q];
        }
        TCGEN05_FENCE_BEFORE();
    }
    __syncthreads();
    if (wid == 7) {
        TCGEN05_RELINQ();
        TCGEN05_DEALLOC(tmem, 256);
    }
#else
    // Fallback (base sm_103 compile pass; never selected at runtime on GB300):
    // correct but slow scalar GEMM so the fat binary stays semantically valid.
    const float* A = (WHICH == 0) ? g_Xr : g_h;
    const float* B = (WHICH == 0) ? g_W1t : g_W2t;
    const float* Ab = A + ((size_t)e * T_TOK + (size_t)mt * TM) * KT;
    const float* Bb = B + ((size_t)e * NTOT + (size_t)nt * TN) * KT;
    __syncthreads();
    for (int idx = tid; idx < TM * TN; idx += 256) {
        int m = idx / TN, n = idx % TN;
        float s = bias_s[n];
        const float* a = Ab + (size_t)m * KT;
        const float* b = Bb + (size_t)n * KT;
        for (int k = 0; k < KT; k++) s += a[k] * b[k];
        if (WHICH == 0) s = rn_tf32(s);
        Cb[((size_t)(e * T_TOK + mt * TM + m)) * NTOT + (size_t)nt * TN + n] = s;
    }
#endif
}

// ---------------- host: tensormap building ----------------
typedef CUresult (*PFN_tmEncode)(CUtensorMap*, CUtensorMapDataType, cuuint32_t, void*,
                                 const cuuint64_t*, const cuuint64_t*, const cuuint32_t*,
                                 const cuuint32_t*, CUtensorMapInterleave, CUtensorMapSwizzle,
                                 CUtensorMapL2promotion, CUtensorMapFloatOOBfill);

static void make_map_f32(PFN_tmEncode enc, CUtensorMap* m, void* base,
                         uint64_t d0, uint64_t d1, uint64_t d2,
                         uint32_t b0, uint32_t b1) {
    cuuint64_t dims[3]    = {d0, d1, d2};
    cuuint64_t strides[2] = {d0 * 4, d0 * d1 * 4};
    cuuint32_t box[3]     = {b0, b1, 1};
    cuuint32_t es[3]      = {1, 1, 1};
    enc(m, CU_TENSOR_MAP_DATA_TYPE_FLOAT32, 3, base, dims, strides, box, es,
        CU_TENSOR_MAP_INTERLEAVE_NONE, CU_TENSOR_MAP_SWIZZLE_128B,
        CU_TENSOR_MAP_L2_PROMOTION_L2_128B, CU_TENSOR_MAP_FLOAT_OOB_FILL_NONE);
}

// ---------------- launch ----------------
extern "C" void kernel_launch(void* const* d_in, const int* in_sizes, int n_in,
                              void* d_out, int out_size) {
    const float* X  = (const float*)d_in[0];
    const float* W1 = (const float*)d_in[1];
    const float* b1 = (const float*)d_in[2];
    const float* W2 = (const float*)d_in[3];
    const float* b2 = (const float*)d_in[4];
    float* out = (float*)d_out;

    // Resolve cuTensorMapEncodeTiled via runtime (no -lcuda link dependency)
    static PFN_tmEncode enc = nullptr;
    if (!enc) {
        void* fn = nullptr;
        cudaDriverEntryPointQueryResult qres;
        cudaGetDriverEntryPoint("cuTensorMapEncodeTiled", &fn, cudaEnableDefault, &qres);
        enc = (PFN_tmEncode)fn;
    }
    void *pXr = nullptr, *pW1t = nullptr, *pW2t = nullptr, *pH = nullptr;
    cudaGetSymbolAddress(&pXr, g_Xr);
    cudaGetSymbolAddress(&pW1t, g_W1t);
    cudaGetSymbolAddress(&pW2t, g_W2t);
    cudaGetSymbolAddress(&pH, g_h);

    // box0 = 32 floats = 128B (SW128 span); box1 = tile rows
    static CUtensorMap tmA1, tmB1, tmA2, tmB2;
    make_map_f32(enc, &tmA1, pXr,  H_DIM, T_TOK, E_EXP, 32, 128);  // A1: X  [e][t][h]
    make_map_f32(enc, &tmB1, pW1t, H_DIM, I_DIM, E_EXP, 32, 256);  // B1: W1t [e][i][h]
    make_map_f32(enc, &tmA2, pH,   I_DIM, T_TOK, E_EXP, 32, 128);  // A2: h  [e][t][i]
    make_map_f32(enc, &tmB2, pW2t, I_DIM, H_DIM, E_EXP, 32, 256);  // B2: W2t [e][h][i]

    constexpr int SMEM = 4096 + 4 * (128 * 32 * 4 + 256 * 32 * 4);  // 200704
    cudaFuncSetAttribute(gemm_tf32_kernel<H_DIM, I_DIM, 0>,
                         cudaFuncAttributeMaxDynamicSharedMemorySize, SMEM);
    cudaFuncSetAttribute(gemm_tf32_kernel<I_DIM, H_DIM, 1>,
                         cudaFuncAttributeMaxDynamicSharedMemorySize, SMEM);

    // prep: RN-round to tf32 bit patterns (+ transpose weights to [n][k])
    round_x_kernel<<<(E_EXP * T_TOK * H_DIM) / (4 * 256), 256>>>((const float4*)X);
    transpose_round_kernel<0><<<dim3(I_DIM / 32, H_DIM / 32, E_EXP), dim3(32, 8)>>>(W1);
    transpose_round_kernel<1><<<dim3(H_DIM / 32, I_DIM / 32, E_EXP), dim3(32, 8)>>>(W2);

    // GEMM1: h = X @ W1 + b1   (grid 4 x 16 x 16 = 1024 CTAs)
    gemm_tf32_kernel<H_DIM, I_DIM, 0>
        <<<dim3(T_TOK / 128, I_DIM / 256, E_EXP), 256, SMEM>>>(tmA1, tmB1, b1, nullptr);
    // GEMM2: y = h @ W2 + b2   (grid 4 x 4 x 16 = 256 CTAs)
    gemm_tf32_kernel<I_DIM, H_DIM, 1>
        <<<dim3(T_TOK / 128, H_DIM / 256, E_EXP), 256, SMEM>>>(tmA2, tmB2, b2, out);
}